// round 4
// baseline (speedup 1.0000x reference)
#include <cuda_runtime.h>
#include <math.h>

#define S_LEN  1024
#define BATCH  4
#define DMODEL 1024
#define NHEAD  16
#define DHEAD  64

// ---------------- device scratch ----------------
// head-major qkv: idx = (((which*BATCH + b)*NHEAD + h)*S_LEN + s)*DHEAD + d
__device__ float g_qkv[3 * BATCH * NHEAD * S_LEN * DHEAD];
__device__ float g_concat[S_LEN * BATCH * DMODEL];   // [row = s*B+b][h*64+d]

// ---------------- helpers ----------------
__device__ __forceinline__ unsigned f2tf(float f) {
    unsigned u;
    asm("cvt.rna.tf32.f32 %0, %1;" : "=r"(u) : "f"(f));
    return u;
}

#define MMA_TF32(d, a, b)                                                        \
    asm volatile(                                                                \
        "mma.sync.aligned.m16n8k8.row.col.f32.tf32.tf32.f32 "                    \
        "{%0,%1,%2,%3}, {%4,%5,%6,%7}, {%8,%9}, {%0,%1,%2,%3};"                  \
        : "+f"((d)[0]), "+f"((d)[1]), "+f"((d)[2]), "+f"((d)[3])                 \
        : "r"((a)[0]), "r"((a)[1]), "r"((a)[2]), "r"((a)[3]),                    \
          "r"((b)[0]), "r"((b)[1]))

// ---------------- TF32 GEMM: 128x128x32 tile, 8 warps, fragment-order smem ----------------
// A frag group (kb,mg): 16 rows x 8 k, 128 words; lane chunk of 4 words = one mma A frag.
//   addr = (kb*8+mg)*128 + ((lane^kb)<<2) + slot, slot = hi + 2*chi
// B frag group (kb,ng): 8 k x 8 n, 64 words; lane chunk of 2 words = one mma B frag.
//   addr = (kb*16+ng)*64 + (((gid*4+tig)^ng)<<1) + hi
template<int QKV>
__device__ __forceinline__ void gemm_body(
    const float* __restrict__ A, const float* __restrict__ Bthr, int ldbf,
    const float* __restrict__ biasP, float* __restrict__ C,
    int lda, int ldc, int m0, int n0)
{
    __shared__ unsigned As[4096];
    __shared__ unsigned Bs[4096];

    const int tid  = threadIdx.x;
    const int lane = tid & 31;
    const int wid  = tid >> 5;
    const int gid  = lane >> 2;
    const int tig  = lane & 3;

    float acc[4][4][4];
#pragma unroll
    for (int mt = 0; mt < 4; ++mt)
#pragma unroll
        for (int nt = 0; nt < 4; ++nt)
#pragma unroll
            for (int r = 0; r < 4; ++r) acc[mt][nt][r] = 0.f;

    // global A mapping
    const int arow  = tid >> 3;              // 0..31
    const int acol  = (tid & 7) << 2;        // k offset 0..28
    const int a_kb  = acol >> 3;
    const int a_chi = (acol >> 2) & 1;
    const int a_gid = arow & 7;
    const int a_hi  = (arow >> 3) & 1;
    const int a_mgb = arow >> 4;
    // global B mapping
    const int b_brow = tid >> 5;             // 0..7 (k row within 8)
    const int bcol   = (tid & 31) << 2;      // n offset 0..124
    const int b_tig  = b_brow & 3;
    const int b_hi   = (b_brow >> 2) & 1;
    const int b_ng   = bcol >> 3;
    const int b_gidb = bcol & 7;

    const float* Ap = A + (size_t)(m0 + arow) * lda + acol;

    float4 ag[4], bg[4];
#pragma unroll
    for (int r = 0; r < 4; ++r) ag[r] = *(const float4*)(Ap + (size_t)(32 * r) * lda);
#pragma unroll
    for (int r = 0; r < 4; ++r) bg[r] = *(const float4*)(Bthr + (size_t)(8 * r) * ldbf);

    for (int k0 = 0; k0 < DMODEL; k0 += 32) {
        __syncthreads();
        // ---- stage A (fragment order) ----
#pragma unroll
        for (int r = 0; r < 4; ++r) {
            unsigned* dst = &As[(a_kb * 8 + a_mgb + 2 * r) * 128 + a_hi + 2 * a_chi];
            dst[(a_gid * 4 + (0 ^ a_kb)) * 4] = f2tf(ag[r].x);
            dst[(a_gid * 4 + (1 ^ a_kb)) * 4] = f2tf(ag[r].y);
            dst[(a_gid * 4 + (2 ^ a_kb)) * 4] = f2tf(ag[r].z);
            dst[(a_gid * 4 + (3 ^ a_kb)) * 4] = f2tf(ag[r].w);
        }
        // ---- stage B (fragment order) ----
#pragma unroll
        for (int r = 0; r < 4; ++r) {
            unsigned* dst = &Bs[(r * 16 + b_ng) * 64 + b_hi];
            dst[((((b_gidb + 0) * 4 + b_tig) ^ b_ng)) * 2] = f2tf(bg[r].x);
            dst[((((b_gidb + 1) * 4 + b_tig) ^ b_ng)) * 2] = f2tf(bg[r].y);
            dst[((((b_gidb + 2) * 4 + b_tig) ^ b_ng)) * 2] = f2tf(bg[r].z);
            dst[((((b_gidb + 3) * 4 + b_tig) ^ b_ng)) * 2] = f2tf(bg[r].w);
        }
        __syncthreads();

        // ---- prefetch next k-tile (overlaps with MMA below) ----
        if (k0 + 32 < DMODEL) {
#pragma unroll
            for (int r = 0; r < 4; ++r)
                ag[r] = *(const float4*)(Ap + (size_t)(32 * r) * lda + (k0 + 32));
#pragma unroll
            for (int r = 0; r < 4; ++r)
                bg[r] = *(const float4*)(Bthr + (size_t)(k0 + 32 + 8 * r) * ldbf);
        }

        // ---- compute ----
#pragma unroll
        for (int kb = 0; kb < 4; ++kb) {
            unsigned af[4][4], bf[4][2];
            const int la = (lane ^ kb) << 2;
#pragma unroll
            for (int mt = 0; mt < 4; ++mt) {
                int mg = (wid >> 2) * 4 + mt;
                uint4 t = *(const uint4*)&As[(kb * 8 + mg) * 128 + la];
                af[mt][0] = t.x; af[mt][1] = t.y; af[mt][2] = t.z; af[mt][3] = t.w;
            }
#pragma unroll
            for (int nt = 0; nt < 4; ++nt) {
                int ng = (wid & 3) * 4 + nt;
                uint2 t = *(const uint2*)&Bs[(kb * 16 + ng) * 64 + ((lane ^ ng) << 1)];
                bf[nt][0] = t.x; bf[nt][1] = t.y;
            }
#pragma unroll
            for (int mt = 0; mt < 4; ++mt)
#pragma unroll
                for (int nt = 0; nt < 4; ++nt)
                    MMA_TF32(acc[mt][nt], af[mt], bf[nt]);
        }
    }

    // ---- epilogue ----
    const int wm = (wid >> 2) * 64;
    const int wn = (wid & 3) * 32;
#pragma unroll
    for (int mt = 0; mt < 4; ++mt) {
        int row0 = m0 + wm + mt * 16 + gid;
#pragma unroll
        for (int nt = 0; nt < 4; ++nt) {
            int col = n0 + wn + nt * 8 + 2 * tig;
            float b0 = biasP[col & 1023], b1 = biasP[(col + 1) & 1023];
            float2 r0 = make_float2(acc[mt][nt][0] + b0, acc[mt][nt][1] + b1);
            float2 r1 = make_float2(acc[mt][nt][2] + b0, acc[mt][nt][3] + b1);
            if (!QKV) {
                *(float2*)&C[(size_t)row0 * ldc + col]       = r0;
                *(float2*)&C[(size_t)(row0 + 8) * ldc + col] = r1;
            } else {
                int which = col >> 10, hh = (col >> 6) & 15, d = col & 63;
                int s0 = row0 >> 2, b0i = row0 & 3;
                int row1 = row0 + 8;
                int s1 = row1 >> 2, b1i = row1 & 3;
                size_t i0 = (((size_t)(which * BATCH + b0i) * NHEAD + hh) * S_LEN + s0) * DHEAD + d;
                size_t i1 = (((size_t)(which * BATCH + b1i) * NHEAD + hh) * S_LEN + s1) * DHEAD + d;
                *(float2*)&C[i0] = r0;
                *(float2*)&C[i1] = r1;
            }
        }
    }
}

// GEMM 1: qkv = {q|k|v} @ W{q|k|v} + b -> head-major scatter (reads weights directly)
__global__ void __launch_bounds__(256, 2) gemm_qkv_kernel(
    const float* __restrict__ q, const float* __restrict__ k, const float* __restrict__ v,
    const float* __restrict__ Wq, const float* __restrict__ Wk, const float* __restrict__ Wv,
    const float* __restrict__ bq, const float* __restrict__ bk, const float* __restrict__ bv) {
    int n0 = blockIdx.x * 128;
    int m0 = blockIdx.y * 128;
    const float* A     = (n0 < 1024) ? q  : (n0 < 2048) ? k  : v;
    const float* Wbase = (n0 < 1024) ? Wq : (n0 < 2048) ? Wk : Wv;
    const float* bias  = (n0 < 1024) ? bq : (n0 < 2048) ? bk : bv;
    int n = n0 + ((threadIdx.x & 31) << 2);
    // W element (d, n) = Wbase[h*65536 + d*64 + kk]; per-thread ptr, k-stride 64
    const float* Bthr = Wbase + ((size_t)((n >> 6) & 15) << 16) + (n & 63)
                      + (threadIdx.x >> 5) * 64;
    gemm_body<1>(A, Bthr, 64, bias, g_qkv, DMODEL, 0, m0, n0);
}

// GEMM 3: out[4096,1024] = g_concat @ Wo + bo
__global__ void __launch_bounds__(256, 2) gemm_out_kernel(
    const float* __restrict__ Wo, const float* __restrict__ bo, float* __restrict__ out) {
    int n0 = blockIdx.x * 128;
    int m0 = blockIdx.y * 128;
    const float* Bthr = Wo + (size_t)(threadIdx.x >> 5) * DMODEL + n0 + ((threadIdx.x & 31) << 2);
    gemm_body<0>(g_concat, Bthr, DMODEL, bo, out, DMODEL, DMODEL, m0, n0);
}

// ---------------- TF32 MMA flash attention (unchanged from R3) ----------------
#define ATTN_SMEM_BYTES ((128 * 68 + 64 * 68 + 64 * 72 + 128 * 68 + 64) * 4)

__global__ void __launch_bounds__(256, 2) attn_kernel(const int* __restrict__ key_mask) {
    extern __shared__ unsigned sm[];
    unsigned* uQ = sm;
    unsigned* uK = uQ + 128 * 68;
    unsigned* uV = uK + 64 * 68;
    unsigned* uP = uV + 64 * 72;
    float* msk   = (float*)(uP + 128 * 68);

    const int b = blockIdx.z, h = blockIdx.y, i0 = blockIdx.x * 128;
    const int tid = threadIdx.x, lane = tid & 31, wid = tid >> 5;
    const int gid = lane >> 2, tig = lane & 3;
    const int wrow = wid * 16;

    const float* Qg = g_qkv + (((size_t)(0 * BATCH + b) * NHEAD + h) * S_LEN + i0) * DHEAD;
    const float* Kg = g_qkv + (((size_t)(1 * BATCH + b) * NHEAD + h) * S_LEN) * DHEAD;
    const float* Vg = g_qkv + (((size_t)(2 * BATCH + b) * NHEAD + h) * S_LEN) * DHEAD;

    {
        const float4* src = (const float4*)Qg;
#pragma unroll
        for (int r = 0; r < 8; ++r) {
            int f = tid + 256 * r;
            int i = f >> 4, d = (f & 15) << 2;
            float4 v = src[f];
            unsigned* dst = &uQ[i * 68 + d];
            dst[0] = f2tf(v.x); dst[1] = f2tf(v.y); dst[2] = f2tf(v.z); dst[3] = f2tf(v.w);
        }
    }

    float m0 = -1e30f, m1 = -1e30f, l0 = 0.f, l1 = 0.f;
    float o[8][4];
#pragma unroll
    for (int nt = 0; nt < 8; ++nt)
#pragma unroll
        for (int r = 0; r < 4; ++r) o[nt][r] = 0.f;

    for (int jt = 0; jt < S_LEN / 64; ++jt) {
        const int j0 = jt * 64;
        __syncthreads();
        {
            const float4* ks = (const float4*)(Kg + (size_t)j0 * DHEAD);
            const float4* vs = (const float4*)(Vg + (size_t)j0 * DHEAD);
#pragma unroll
            for (int r = 0; r < 4; ++r) {
                int f = tid + 256 * r;
                int j = f >> 4, d = (f & 15) << 2;
                float4 kv = ks[f];
                unsigned* kd = &uK[j * 68 + d];
                kd[0] = f2tf(kv.x); kd[1] = f2tf(kv.y); kd[2] = f2tf(kv.z); kd[3] = f2tf(kv.w);
                float4 vv = vs[f];
                unsigned* vd = &uV[j * 72 + d];
                vd[0] = f2tf(vv.x); vd[1] = f2tf(vv.y); vd[2] = f2tf(vv.z); vd[3] = f2tf(vv.w);
            }
            if (tid < 64)
                msk[tid] = key_mask[(j0 + tid) * BATCH + b] ? -1e18f : 0.f;
        }
        __syncthreads();

        float s[8][4];
#pragma unroll
        for (int nt = 0; nt < 8; ++nt)
#pragma unroll
            for (int r = 0; r < 4; ++r) s[nt][r] = 0.f;
#pragma unroll
        for (int kb = 0; kb < 64; kb += 8) {
            unsigned a[4];
            a[0] = uQ[(wrow + gid) * 68 + kb + tig];
            a[1] = uQ[(wrow + gid + 8) * 68 + kb + tig];
            a[2] = uQ[(wrow + gid) * 68 + kb + tig + 4];
            a[3] = uQ[(wrow + gid + 8) * 68 + kb + tig + 4];
#pragma unroll
            for (int nt = 0; nt < 8; ++nt) {
                unsigned bfr[2];
                bfr[0] = uK[(nt * 8 + gid) * 68 + kb + tig];
                bfr[1] = uK[(nt * 8 + gid) * 68 + kb + tig + 4];
                MMA_TF32(s[nt], a, bfr);
            }
        }

        float mx0 = -1e30f, mx1 = -1e30f;
#pragma unroll
        for (int nt = 0; nt < 8; ++nt) {
            float q0 = msk[nt * 8 + 2 * tig], q1 = msk[nt * 8 + 2 * tig + 1];
            s[nt][0] = fmaf(s[nt][0], 0.125f, q0);
            s[nt][1] = fmaf(s[nt][1], 0.125f, q1);
            s[nt][2] = fmaf(s[nt][2], 0.125f, q0);
            s[nt][3] = fmaf(s[nt][3], 0.125f, q1);
            mx0 = fmaxf(mx0, fmaxf(s[nt][0], s[nt][1]));
            mx1 = fmaxf(mx1, fmaxf(s[nt][2], s[nt][3]));
        }
        mx0 = fmaxf(mx0, __shfl_xor_sync(0xffffffffu, mx0, 1));
        mx0 = fmaxf(mx0, __shfl_xor_sync(0xffffffffu, mx0, 2));
        mx1 = fmaxf(mx1, __shfl_xor_sync(0xffffffffu, mx1, 1));
        mx1 = fmaxf(mx1, __shfl_xor_sync(0xffffffffu, mx1, 2));

        float mn0 = fmaxf(m0, mx0), mn1 = fmaxf(m1, mx1);
        float la0 = 0.f, la1 = 0.f;
        unsigned* p0row = &uP[(wrow + gid) * 68];
        unsigned* p1row = &uP[(wrow + gid + 8) * 68];
#pragma unroll
        for (int nt = 0; nt < 8; ++nt) {
            float p0 = __expf(s[nt][0] - mn0);
            float p1 = __expf(s[nt][1] - mn0);
            float p2 = __expf(s[nt][2] - mn1);
            float p3 = __expf(s[nt][3] - mn1);
            la0 += p0 + p1; la1 += p2 + p3;
            int c = nt * 8 + 2 * tig;
            p0row[c] = f2tf(p0); p0row[c + 1] = f2tf(p1);
            p1row[c] = f2tf(p2); p1row[c + 1] = f2tf(p3);
        }
        la0 += __shfl_xor_sync(0xffffffffu, la0, 1);
        la0 += __shfl_xor_sync(0xffffffffu, la0, 2);
        la1 += __shfl_xor_sync(0xffffffffu, la1, 1);
        la1 += __shfl_xor_sync(0xffffffffu, la1, 2);

        float al0 = __expf(m0 - mn0), al1 = __expf(m1 - mn1);
        l0 = l0 * al0 + la0;
        l1 = l1 * al1 + la1;
        m0 = mn0; m1 = mn1;
#pragma unroll
        for (int nt = 0; nt < 8; ++nt) {
            o[nt][0] *= al0; o[nt][1] *= al0;
            o[nt][2] *= al1; o[nt][3] *= al1;
        }
        __syncwarp();

#pragma unroll
        for (int kb = 0; kb < 64; kb += 8) {
            unsigned a[4];
            a[0] = uP[(wrow + gid) * 68 + kb + tig];
            a[1] = uP[(wrow + gid + 8) * 68 + kb + tig];
            a[2] = uP[(wrow + gid) * 68 + kb + tig + 4];
            a[3] = uP[(wrow + gid + 8) * 68 + kb + tig + 4];
#pragma unroll
            for (int nt = 0; nt < 8; ++nt) {
                unsigned bfr[2];
                bfr[0] = uV[(kb + tig) * 72 + nt * 8 + gid];
                bfr[1] = uV[(kb + tig + 4) * 72 + nt * 8 + gid];
                MMA_TF32(o[nt], a, bfr);
            }
        }
    }

    float inv0 = 1.f / l0, inv1 = 1.f / l1;
    int r0 = i0 + wrow + gid;
#pragma unroll
    for (int nt = 0; nt < 8; ++nt) {
        int col = h * 64 + nt * 8 + 2 * tig;
        *(float2*)&g_concat[(size_t)(r0 * BATCH + b) * DMODEL + col] =
            make_float2(o[nt][0] * inv0, o[nt][1] * inv0);
        *(float2*)&g_concat[(size_t)((r0 + 8) * BATCH + b) * DMODEL + col] =
            make_float2(o[nt][2] * inv1, o[nt][3] * inv1);
    }
}

// ---------------- entry point ----------------
extern "C" void kernel_launch(void* const* d_in, const int* in_sizes, int n_in,
                              void* d_out, int out_size) {
    const float* query    = (const float*)d_in[0];
    const float* key      = (const float*)d_in[1];
    const float* value    = (const float*)d_in[2];
    const int*   key_mask = (const int*)  d_in[3];
    const float* Wq = (const float*)d_in[4];
    const float* bq = (const float*)d_in[5];
    const float* Wk = (const float*)d_in[6];
    const float* bk = (const float*)d_in[7];
    const float* Wv = (const float*)d_in[8];
    const float* bv = (const float*)d_in[9];
    const float* Wo = (const float*)d_in[10];
    const float* bo = (const float*)d_in[11];
    float* out = (float*)d_out;

    cudaFuncSetAttribute(attn_kernel, cudaFuncAttributeMaxDynamicSharedMemorySize,
                         ATTN_SMEM_BYTES);

    gemm_qkv_kernel<<<dim3(3 * DMODEL / 128, S_LEN * BATCH / 128), 256>>>(
        query, key, value, Wq, Wk, Wv, bq, bk, bv);
    attn_kernel<<<dim3(S_LEN / 128, NHEAD, BATCH), 256, ATTN_SMEM_BYTES>>>(key_mask);
    gemm_out_kernel<<<dim3(DMODEL / 128, S_LEN * BATCH / 128), 256>>>(Wo, bo, out);
}